// round 3
// baseline (speedup 1.0000x reference)
#include <cuda_runtime.h>
#include <cstddef>
#include <cstdint>

// Problem constants
#define BATCH 2
#define SEQ   2048
#define DMODEL 2048
#define NHEADS 16
#define HDIM  128
#define D3    (3 * DMODEL)
#define MROWS (BATCH * SEQ)   // 4096

// ---------------- scratch (no allocations allowed) ----------------
__device__ float g_qkv[(size_t)MROWS * D3];                       // [B*S, 3D]
__device__ float g_Q[(size_t)BATCH * NHEADS * SEQ * HDIM];        // [B,H,S,hd]
__device__ float g_K[(size_t)BATCH * NHEADS * SEQ * HDIM];
__device__ float g_V[(size_t)BATCH * NHEADS * SEQ * HDIM];
__device__ float g_attn[(size_t)MROWS * DMODEL];                  // [B*S, D]
__device__ float g_cos[SEQ * 64];
__device__ float g_sin[SEQ * 64];

// ---------------- RoPE table ----------------
__global__ void rope_table_kernel() {
    int s = blockIdx.x;
    int j = threadIdx.x;            // 0..63
    float inv = powf(10000.0f, -(float)j / 64.0f);
    float ang = (float)s * inv;
    g_cos[s * 64 + j] = cosf(ang);
    g_sin[s * 64 + j] = sinf(ang);
}

// ---------------- SGEMM: C[M,N] = A[M,K] * B[K,N], all row-major ----------------
// BM=128, BN=128, BK=16, 256 threads, 8x8 per-thread tile.
__global__ __launch_bounds__(256) void sgemm_kernel(
    const float* __restrict__ A, const float* __restrict__ B, float* __restrict__ C,
    int M, int N, int K_)
{
    __shared__ float As[16][132];   // [k][m]
    __shared__ float Bs[16][132];   // [k][n]

    const int tid = threadIdx.x;
    const int m0 = blockIdx.y * 128;
    const int n0 = blockIdx.x * 128;
    const int tm = tid >> 4;        // 0..15
    const int tn = tid & 15;        // 0..15

    const int arow  = tid >> 2;         // 0..63
    const int acol4 = (tid & 3) << 2;   // 0,4,8,12
    const int brow  = tid >> 5;         // 0..7
    const int bcol4 = (tid & 31) << 2;  // 0..124

    float acc[8][8];
    #pragma unroll
    for (int i = 0; i < 8; i++)
        #pragma unroll
        for (int j = 0; j < 8; j++) acc[i][j] = 0.0f;

    for (int k0 = 0; k0 < K_; k0 += 16) {
        float4 a0 = *(const float4*)&A[(size_t)(m0 + arow)      * K_ + k0 + acol4];
        float4 a1 = *(const float4*)&A[(size_t)(m0 + arow + 64) * K_ + k0 + acol4];
        float4 b0 = *(const float4*)&B[(size_t)(k0 + brow)     * N + n0 + bcol4];
        float4 b1 = *(const float4*)&B[(size_t)(k0 + brow + 8) * N + n0 + bcol4];

        As[acol4 + 0][arow] = a0.x; As[acol4 + 1][arow] = a0.y;
        As[acol4 + 2][arow] = a0.z; As[acol4 + 3][arow] = a0.w;
        As[acol4 + 0][arow + 64] = a1.x; As[acol4 + 1][arow + 64] = a1.y;
        As[acol4 + 2][arow + 64] = a1.z; As[acol4 + 3][arow + 64] = a1.w;
        *(float4*)&Bs[brow][bcol4]     = b0;
        *(float4*)&Bs[brow + 8][bcol4] = b1;
        __syncthreads();

        #pragma unroll
        for (int k = 0; k < 16; k++) {
            float4 ra0 = *(float4*)&As[k][tm * 8];
            float4 ra1 = *(float4*)&As[k][tm * 8 + 4];
            float4 rb0 = *(float4*)&Bs[k][tn * 8];
            float4 rb1 = *(float4*)&Bs[k][tn * 8 + 4];
            float a_[8] = {ra0.x, ra0.y, ra0.z, ra0.w, ra1.x, ra1.y, ra1.z, ra1.w};
            float b_[8] = {rb0.x, rb0.y, rb0.z, rb0.w, rb1.x, rb1.y, rb1.z, rb1.w};
            #pragma unroll
            for (int i = 0; i < 8; i++)
                #pragma unroll
                for (int j = 0; j < 8; j++)
                    acc[i][j] += a_[i] * b_[j];
        }
        __syncthreads();
    }

    #pragma unroll
    for (int i = 0; i < 8; i++) {
        float* crow = C + (size_t)(m0 + tm * 8 + i) * N + n0 + tn * 8;
        float4 o0 = make_float4(acc[i][0], acc[i][1], acc[i][2], acc[i][3]);
        float4 o1 = make_float4(acc[i][4], acc[i][5], acc[i][6], acc[i][7]);
        *(float4*)crow       = o0;
        *((float4*)crow + 1) = o1;
    }
}

// ---------------- RoPE + split + transpose ----------------
// qkv[B*S, 3D] -> Q/K/V [B,H,S,hd] with RoPE on Q,K
__global__ __launch_bounds__(256) void rope_split_kernel(
    const float* __restrict__ qkv,
    float* __restrict__ Q, float* __restrict__ K, float* __restrict__ V)
{
    int bs = blockIdx.x;           // 0..B*S-1
    int b = bs / SEQ, s = bs % SEQ;
    const float* row = qkv + (size_t)bs * D3;

    for (int e = threadIdx.x; e < DMODEL; e += 256) {
        int h = e >> 7, d = e & 127, j = d & 63;
        float c  = g_cos[s * 64 + j];
        float sn = g_sin[s * 64 + j];
        float qv = row[e];
        float kv = row[DMODEL + e];
        float vv = row[2 * DMODEL + e];
        int po = (d < 64) ? (e + 64) : (e - 64);
        float sgn = (d < 64) ? -1.0f : 1.0f;
        float qp = row[po];
        float kp = row[DMODEL + po];
        float qo = qv * c + sgn * qp * sn;
        float ko = kv * c + sgn * kp * sn;
        size_t oidx = ((size_t)(b * NHEADS + h) * SEQ + s) * HDIM + d;
        Q[oidx] = qo;
        K[oidx] = ko;
        V[oidx] = vv;
    }
}

// ---------------- Flash-style attention ----------------
// grid: (SEQ/64, B*H), 256 threads, dynamic smem.
// Per CTA: 64 q-rows x hd=128, stream KV in 64-row tiles with online softmax.
#define ATTN_SMEM_FLOATS (128*68 + 128*68 + 64*132 + 64*68 + 3*64)
#define ATTN_SMEM_BYTES  (ATTN_SMEM_FLOATS * 4)

__global__ __launch_bounds__(256) void attn_kernel(
    const float* __restrict__ Qg, const float* __restrict__ Kg,
    const float* __restrict__ Vg, float* __restrict__ Og)
{
    extern __shared__ float sm[];
    float* Qs = sm;                       // [128][68]  (d-major, transposed)
    float* Ks = Qs + 128 * 68;            // [128][68]
    float* Vs = Ks + 128 * 68;            // [64][132]  (j-major)
    float* Ps = Vs + 64 * 132;            // [64][68]   (j-major, transposed scores/probs)
    float* m_s    = Ps + 64 * 68;
    float* l_s    = m_s + 64;
    float* corr_s = l_s + 64;

    const int tid = threadIdx.x;
    const int bh  = blockIdx.y;           // b*H + h
    const int s0  = blockIdx.x * 64;
    const float* Qb = Qg + (size_t)bh * SEQ * HDIM;
    const float* Kb = Kg + (size_t)bh * SEQ * HDIM;
    const float* Vb = Vg + (size_t)bh * SEQ * HDIM;

    // load Q tile transposed: Qs[d][r]
    #pragma unroll
    for (int i = 0; i < 8; i++) {
        int f4 = tid + i * 256;
        int r = f4 >> 5, d4 = (f4 & 31) << 2;
        float4 q = *(const float4*)&Qb[(size_t)(s0 + r) * HDIM + d4];
        Qs[(d4 + 0) * 68 + r] = q.x;
        Qs[(d4 + 1) * 68 + r] = q.y;
        Qs[(d4 + 2) * 68 + r] = q.z;
        Qs[(d4 + 3) * 68 + r] = q.w;
    }
    if (tid < 64) { m_s[tid] = -1e30f; l_s[tid] = 0.0f; }
    __syncthreads();

    const int tm = tid >> 4, tn = tid & 15;
    const int r0 = tm * 4;          // AV / scores row base
    const int d0 = tn * 8;          // AV col base
    const int sc0 = tn * 4;         // scores col base
    const int rr = tid >> 2, q4 = tid & 3;  // softmax mapping
    const float scale = 0.08838834764831845f;  // 1/sqrt(128)

    float acc[4][8];
    #pragma unroll
    for (int i = 0; i < 4; i++)
        #pragma unroll
        for (int j = 0; j < 8; j++) acc[i][j] = 0.0f;

    for (int kt = 0; kt < SEQ / 64; kt++) {
        const int ks0 = kt * 64;
        // load K (transposed) and V (direct)
        #pragma unroll
        for (int i = 0; i < 8; i++) {
            int f4 = tid + i * 256;
            int r = f4 >> 5, d4 = (f4 & 31) << 2;
            float4 kv = *(const float4*)&Kb[(size_t)(ks0 + r) * HDIM + d4];
            Ks[(d4 + 0) * 68 + r] = kv.x;
            Ks[(d4 + 1) * 68 + r] = kv.y;
            Ks[(d4 + 2) * 68 + r] = kv.z;
            Ks[(d4 + 3) * 68 + r] = kv.w;
            float4 vv = *(const float4*)&Vb[(size_t)(ks0 + r) * HDIM + d4];
            *(float4*)&Vs[r * 132 + d4] = vv;
        }
        __syncthreads();

        // scores: 4x4 register tile over [64 r][64 j], k-dim = d(128)
        float accs[4][4];
        #pragma unroll
        for (int i = 0; i < 4; i++)
            #pragma unroll
            for (int j = 0; j < 4; j++) accs[i][j] = 0.0f;

        #pragma unroll 8
        for (int d = 0; d < 128; d++) {
            float4 qa = *(float4*)&Qs[d * 68 + r0];
            float4 kb = *(float4*)&Ks[d * 68 + sc0];
            float a_[4] = {qa.x, qa.y, qa.z, qa.w};
            float b_[4] = {kb.x, kb.y, kb.z, kb.w};
            #pragma unroll
            for (int i = 0; i < 4; i++)
                #pragma unroll
                for (int j = 0; j < 4; j++)
                    accs[i][j] += a_[i] * b_[j];
        }
        #pragma unroll
        for (int jj = 0; jj < 4; jj++)
            #pragma unroll
            for (int ii = 0; ii < 4; ii++)
                Ps[(sc0 + jj) * 68 + (r0 + ii)] = accs[ii][jj] * scale;
        __syncthreads();

        // online softmax: 4 threads per row (quad = adjacent lanes)
        float mv = -1e30f;
        #pragma unroll
        for (int jj = 0; jj < 16; jj++)
            mv = fmaxf(mv, Ps[(q4 + 4 * jj) * 68 + rr]);
        mv = fmaxf(mv, __shfl_xor_sync(0xffffffffu, mv, 1));
        mv = fmaxf(mv, __shfl_xor_sync(0xffffffffu, mv, 2));
        float m_old = m_s[rr];
        float m_new = fmaxf(m_old, mv);
        float sum = 0.0f;
        #pragma unroll
        for (int jj = 0; jj < 16; jj++) {
            int j = q4 + 4 * jj;
            float p = expf(Ps[j * 68 + rr] - m_new);
            Ps[j * 68 + rr] = p;
            sum += p;
        }
        sum += __shfl_xor_sync(0xffffffffu, sum, 1);
        sum += __shfl_xor_sync(0xffffffffu, sum, 2);
        if (q4 == 0) {
            float corr = expf(m_old - m_new);
            l_s[rr] = l_s[rr] * corr + sum;
            m_s[rr] = m_new;
            corr_s[rr] = corr;
        }
        __syncthreads();

        // AV: acc[4 rows][8 cols] += P[r][j] * V[j][d]
        float c_[4] = {corr_s[r0], corr_s[r0 + 1], corr_s[r0 + 2], corr_s[r0 + 3]};
        #pragma unroll
        for (int i = 0; i < 4; i++)
            #pragma unroll
            for (int j = 0; j < 8; j++) acc[i][j] *= c_[i];

        #pragma unroll 4
        for (int j = 0; j < 64; j++) {
            float4 p4 = *(float4*)&Ps[j * 68 + r0];
            float4 v0 = *(float4*)&Vs[j * 132 + d0];
            float4 v1 = *(float4*)&Vs[j * 132 + d0 + 4];
            float pv[4] = {p4.x, p4.y, p4.z, p4.w};
            float vv[8] = {v0.x, v0.y, v0.z, v0.w, v1.x, v1.y, v1.z, v1.w};
            #pragma unroll
            for (int i = 0; i < 4; i++)
                #pragma unroll
                for (int jj = 0; jj < 8; jj++)
                    acc[i][jj] += pv[i] * vv[jj];
        }
        __syncthreads();
    }

    // epilogue: normalize and store to [B*S, D] layout (col = h*128 + d)
    const int b = bh >> 4, h = bh & 15;
    #pragma unroll
    for (int i = 0; i < 4; i++) {
        float inv_l = 1.0f / l_s[r0 + i];
        size_t grow = (size_t)(b * SEQ + s0 + r0 + i) * DMODEL + h * HDIM + d0;
        float4 o0 = make_float4(acc[i][0] * inv_l, acc[i][1] * inv_l,
                                acc[i][2] * inv_l, acc[i][3] * inv_l);
        float4 o1 = make_float4(acc[i][4] * inv_l, acc[i][5] * inv_l,
                                acc[i][6] * inv_l, acc[i][7] * inv_l);
        *(float4*)&Og[grow]     = o0;
        *(float4*)&Og[grow + 4] = o1;
    }
}

// ---------------- launch ----------------
extern "C" void kernel_launch(void* const* d_in, const int* in_sizes, int n_in,
                              void* d_out, int out_size)
{
    const float* x     = (const float*)d_in[0];
    const float* w_qkv = (const float*)d_in[1];
    const float* w_out = (const float*)d_in[2];
    float* out = (float*)d_out;

    float *qkv, *Q, *K, *V, *attn;
    cudaGetSymbolAddress((void**)&qkv,  g_qkv);
    cudaGetSymbolAddress((void**)&Q,    g_Q);
    cudaGetSymbolAddress((void**)&K,    g_K);
    cudaGetSymbolAddress((void**)&V,    g_V);
    cudaGetSymbolAddress((void**)&attn, g_attn);

    cudaFuncSetAttribute(attn_kernel, cudaFuncAttributeMaxDynamicSharedMemorySize,
                         ATTN_SMEM_BYTES);

    rope_table_kernel<<<SEQ, 64>>>();
    // qkv = x @ w_qkv   [4096,2048]x[2048,6144]
    sgemm_kernel<<<dim3(D3 / 128, MROWS / 128), 256>>>(x, w_qkv, qkv, MROWS, D3, DMODEL);
    // rope + split
    rope_split_kernel<<<MROWS, 256>>>(qkv, Q, K, V);
    // attention
    attn_kernel<<<dim3(SEQ / 64, BATCH * NHEADS), 256, ATTN_SMEM_BYTES>>>(Q, K, V, attn);
    // out = attn @ w_out  [4096,2048]x[2048,2048]
    sgemm_kernel<<<dim3(DMODEL / 128, MROWS / 128), 256>>>(attn, w_out, out, MROWS, DMODEL, DMODEL);
}

// round 7
// speedup vs baseline: 1.4713x; 1.4713x over previous
#include <cuda_runtime.h>
#include <cstddef>
#include <cstdint>

// Problem constants
#define BATCH 2
#define SEQ   2048
#define DMODEL 2048
#define NHEADS 16
#define HDIM  128
#define D3    (3 * DMODEL)
#define MROWS (BATCH * SEQ)   // 4096

// ---------------- scratch (no allocations allowed) ----------------
__device__ float g_qkv[(size_t)MROWS * D3];                       // [B*S, 3D]
__device__ float g_Q[(size_t)BATCH * NHEADS * SEQ * HDIM];        // [B,H,S,hd]
__device__ float g_K[(size_t)BATCH * NHEADS * SEQ * HDIM];
__device__ float g_V[(size_t)BATCH * NHEADS * SEQ * HDIM];
__device__ float g_attn[(size_t)MROWS * DMODEL];                  // [B*S, D]
__device__ float g_cos[SEQ * 64];
__device__ float g_sin[SEQ * 64];

// ---------------- helpers ----------------
__device__ __forceinline__ float to_tf32(float x) {
    float r;
    asm("cvt.rna.tf32.f32 %0, %1;" : "=f"(r) : "f"(x));
    return r;
}

// m16n8k8 tf32 warp MMA (base PTX, sm_80+; lowers to legacy HMMA on sm_103)
__device__ __forceinline__ void mma_tf32(float c[4],
                                         uint32_t a0, uint32_t a1, uint32_t a2, uint32_t a3,
                                         uint32_t b0, uint32_t b1) {
    asm volatile(
        "mma.sync.aligned.m16n8k8.row.col.f32.tf32.tf32.f32 "
        "{%0,%1,%2,%3}, {%4,%5,%6,%7}, {%8,%9}, {%0,%1,%2,%3};"
        : "+f"(c[0]), "+f"(c[1]), "+f"(c[2]), "+f"(c[3])
        : "r"(a0), "r"(a1), "r"(a2), "r"(a3), "r"(b0), "r"(b1));
}

// ---------------- RoPE table ----------------
__global__ void rope_table_kernel() {
    int s = blockIdx.x;
    int j = threadIdx.x;            // 0..63
    float inv = powf(10000.0f, -(float)j / 64.0f);
    float ang = (float)s * inv;
    g_cos[s * 64 + j] = cosf(ang);
    g_sin[s * 64 + j] = sinf(ang);
}

// ================= tf32 mma.sync GEMM: C[M,N] = A[M,K] * B[K,N] =================
// Tile 128x128, BK=32, 256 threads (8 warps, 2x4), warp tile 64x32 (4x4 frags).
// Smem: A [2][128][36] (row-major m,k), B [2][32][136] (row-major k,n).
#define GMM_A_STRIDE 36
#define GMM_B_STRIDE 136
#define GMM_A_FLOATS (128 * GMM_A_STRIDE)   // 4608
#define GMM_B_FLOATS (32 * GMM_B_STRIDE)    // 4352
#define GMM_SMEM_FLOATS (2 * GMM_A_FLOATS + 2 * GMM_B_FLOATS)   // 17920
#define GMM_SMEM_BYTES  (GMM_SMEM_FLOATS * 4)                   // 71680

__global__ __launch_bounds__(256) void tf32_mma_gemm(
    const float* __restrict__ A, const float* __restrict__ B, float* __restrict__ C,
    int M, int N, int K_)
{
    extern __shared__ float sm[];
    float* Asm = sm;                        // [2][128][36]
    float* Bsm = sm + 2 * GMM_A_FLOATS;     // [2][32][136]

    const int tid = threadIdx.x;
    const int wid = tid >> 5, lane = tid & 31;
    const int g = lane >> 2, t = lane & 3;
    const int wm = wid >> 2, wn = wid & 3;
    const int m0 = blockIdx.y * 128, n0 = blockIdx.x * 128;
    const int mbase = wm * 64, nbase = wn * 32;

    float4 apref[4], bpref[4];

    // --- global prefetch of tile kt into registers ---
    #define LOADG(kt) do { \
        _Pragma("unroll") \
        for (int i = 0; i < 4; i++) { \
            int f4 = tid + i * 256; \
            int r = f4 >> 3, c = (f4 & 7) << 2; \
            apref[i] = *(const float4*)&A[(size_t)(m0 + r) * K_ + (kt) * 32 + c]; \
            int rb = f4 >> 5, cb = (f4 & 31) << 2; \
            bpref[i] = *(const float4*)&B[(size_t)((kt) * 32 + rb) * N + n0 + cb]; \
        } \
    } while (0)

    // --- store register tile into smem buffer (with tf32 rounding) ---
    #define STORES(buf) do { \
        _Pragma("unroll") \
        for (int i = 0; i < 4; i++) { \
            int f4 = tid + i * 256; \
            int r = f4 >> 3, c = (f4 & 7) << 2; \
            float4 v = apref[i]; \
            v.x = to_tf32(v.x); v.y = to_tf32(v.y); v.z = to_tf32(v.z); v.w = to_tf32(v.w); \
            *(float4*)&Asm[(buf) * GMM_A_FLOATS + r * GMM_A_STRIDE + c] = v; \
            int rb = f4 >> 5, cb = (f4 & 31) << 2; \
            float4 w = bpref[i]; \
            w.x = to_tf32(w.x); w.y = to_tf32(w.y); w.z = to_tf32(w.z); w.w = to_tf32(w.w); \
            *(float4*)&Bsm[(buf) * GMM_B_FLOATS + rb * GMM_B_STRIDE + cb] = w; \
        } \
    } while (0)

    float acc[4][4][4];
    #pragma unroll
    for (int mf = 0; mf < 4; mf++)
        #pragma unroll
        for (int nf = 0; nf < 4; nf++)
            #pragma unroll
            for (int q = 0; q < 4; q++) acc[mf][nf][q] = 0.0f;

    const int KT = K_ / 32;
    LOADG(0);
    STORES(0);
    __syncthreads();

    for (int kt = 0; kt < KT; kt++) {
        const int buf = kt & 1;
        if (kt + 1 < KT) LOADG(kt + 1);

        const float* Ab = &Asm[buf * GMM_A_FLOATS];
        const float* Bb = &Bsm[buf * GMM_B_FLOATS];
        #pragma unroll
        for (int ks = 0; ks < 4; ks++) {
            const int k = ks * 8;
            uint32_t af[4][4];
            #pragma unroll
            for (int mf = 0; mf < 4; mf++) {
                const int row = mbase + mf * 16 + g;
                af[mf][0] = __float_as_uint(Ab[row * GMM_A_STRIDE + k + t]);
                af[mf][1] = __float_as_uint(Ab[(row + 8) * GMM_A_STRIDE + k + t]);
                af[mf][2] = __float_as_uint(Ab[row * GMM_A_STRIDE + k + t + 4]);
                af[mf][3] = __float_as_uint(Ab[(row + 8) * GMM_A_STRIDE + k + t + 4]);
            }
            uint32_t bfr[4][2];
            #pragma unroll
            for (int nf = 0; nf < 4; nf++) {
                const int col = nbase + nf * 8 + g;
                bfr[nf][0] = __float_as_uint(Bb[(k + t) * GMM_B_STRIDE + col]);
                bfr[nf][1] = __float_as_uint(Bb[(k + t + 4) * GMM_B_STRIDE + col]);
            }
            #pragma unroll
            for (int mf = 0; mf < 4; mf++)
                #pragma unroll
                for (int nf = 0; nf < 4; nf++)
                    mma_tf32(acc[mf][nf], af[mf][0], af[mf][1], af[mf][2], af[mf][3],
                             bfr[nf][0], bfr[nf][1]);
        }

        if (kt + 1 < KT) {
            STORES(buf ^ 1);        // other buffer: no reader this iteration
            __syncthreads();
        }
    }

    // epilogue: C frag rows (g, g+8), cols (2t, 2t+1)
    #pragma unroll
    for (int mf = 0; mf < 4; mf++) {
        #pragma unroll
        for (int nf = 0; nf < 4; nf++) {
            const int row = m0 + mbase + mf * 16 + g;
            const int col = n0 + nbase + nf * 8 + 2 * t;
            *(float2*)&C[(size_t)row * N + col] =
                make_float2(acc[mf][nf][0], acc[mf][nf][1]);
            *(float2*)&C[(size_t)(row + 8) * N + col] =
                make_float2(acc[mf][nf][2], acc[mf][nf][3]);
        }
    }
    #undef LOADG
    #undef STORES
}

// ---------------- RoPE + split + transpose ----------------
__global__ __launch_bounds__(256) void rope_split_kernel(
    const float* __restrict__ qkv,
    float* __restrict__ Q, float* __restrict__ K, float* __restrict__ V)
{
    int bs = blockIdx.x;           // 0..B*S-1
    int b = bs / SEQ, s = bs % SEQ;
    const float* row = qkv + (size_t)bs * D3;

    for (int e = threadIdx.x; e < DMODEL; e += 256) {
        int h = e >> 7, d = e & 127, j = d & 63;
        float c  = g_cos[s * 64 + j];
        float sn = g_sin[s * 64 + j];
        float qv = row[e];
        float kv = row[DMODEL + e];
        float vv = row[2 * DMODEL + e];
        int po = (d < 64) ? (e + 64) : (e - 64);
        float sgn = (d < 64) ? -1.0f : 1.0f;
        float qp = row[po];
        float kp = row[DMODEL + po];
        float qo = qv * c + sgn * qp * sn;
        float ko = kv * c + sgn * kp * sn;
        size_t oidx = ((size_t)(b * NHEADS + h) * SEQ + s) * HDIM + d;
        Q[oidx] = qo;
        K[oidx] = ko;
        V[oidx] = vv;
    }
}

// ---------------- Flash-style attention (unchanged, known-good) ----------------
#define ATTN_SMEM_FLOATS (128*68 + 128*68 + 64*132 + 64*68 + 3*64)
#define ATTN_SMEM_BYTES  (ATTN_SMEM_FLOATS * 4)

__global__ __launch_bounds__(256) void attn_kernel(
    const float* __restrict__ Qg, const float* __restrict__ Kg,
    const float* __restrict__ Vg, float* __restrict__ Og)
{
    extern __shared__ float smf[];
    float* Qs = smf;                      // [128][68]  (d-major, transposed)
    float* Ks = Qs + 128 * 68;            // [128][68]
    float* Vs = Ks + 128 * 68;            // [64][132]  (j-major)
    float* Ps = Vs + 64 * 132;            // [64][68]   (j-major, transposed scores/probs)
    float* m_s    = Ps + 64 * 68;
    float* l_s    = m_s + 64;
    float* corr_s = l_s + 64;

    const int tid = threadIdx.x;
    const int bh  = blockIdx.y;           // b*H + h
    const int s0  = blockIdx.x * 64;
    const float* Qb = Qg + (size_t)bh * SEQ * HDIM;
    const float* Kb = Kg + (size_t)bh * SEQ * HDIM;
    const float* Vb = Vg + (size_t)bh * SEQ * HDIM;

    #pragma unroll
    for (int i = 0; i < 8; i++) {
        int f4 = tid + i * 256;
        int r = f4 >> 5, d4 = (f4 & 31) << 2;
        float4 q = *(const float4*)&Qb[(size_t)(s0 + r) * HDIM + d4];
        Qs[(d4 + 0) * 68 + r] = q.x;
        Qs[(d4 + 1) * 68 + r] = q.y;
        Qs[(d4 + 2) * 68 + r] = q.z;
        Qs[(d4 + 3) * 68 + r] = q.w;
    }
    if (tid < 64) { m_s[tid] = -1e30f; l_s[tid] = 0.0f; }
    __syncthreads();

    const int tm = tid >> 4, tn = tid & 15;
    const int r0 = tm * 4;
    const int d0 = tn * 8;
    const int sc0 = tn * 4;
    const int rr = tid >> 2, q4 = tid & 3;
    const float scale = 0.08838834764831845f;  // 1/sqrt(128)

    float acc[4][8];
    #pragma unroll
    for (int i = 0; i < 4; i++)
        #pragma unroll
        for (int j = 0; j < 8; j++) acc[i][j] = 0.0f;

    for (int kt = 0; kt < SEQ / 64; kt++) {
        const int ks0 = kt * 64;
        #pragma unroll
        for (int i = 0; i < 8; i++) {
            int f4 = tid + i * 256;
            int r = f4 >> 5, d4 = (f4 & 31) << 2;
            float4 kv = *(const float4*)&Kb[(size_t)(ks0 + r) * HDIM + d4];
            Ks[(d4 + 0) * 68 + r] = kv.x;
            Ks[(d4 + 1) * 68 + r] = kv.y;
            Ks[(d4 + 2) * 68 + r] = kv.z;
            Ks[(d4 + 3) * 68 + r] = kv.w;
            float4 vv = *(const float4*)&Vb[(size_t)(ks0 + r) * HDIM + d4];
            *(float4*)&Vs[r * 132 + d4] = vv;
        }
        __syncthreads();

        float accs[4][4];
        #pragma unroll
        for (int i = 0; i < 4; i++)
            #pragma unroll
            for (int j = 0; j < 4; j++) accs[i][j] = 0.0f;

        #pragma unroll 8
        for (int d = 0; d < 128; d++) {
            float4 qa = *(float4*)&Qs[d * 68 + r0];
            float4 kb = *(float4*)&Ks[d * 68 + sc0];
            float a_[4] = {qa.x, qa.y, qa.z, qa.w};
            float b_[4] = {kb.x, kb.y, kb.z, kb.w};
            #pragma unroll
            for (int i = 0; i < 4; i++)
                #pragma unroll
                for (int j = 0; j < 4; j++)
                    accs[i][j] += a_[i] * b_[j];
        }
        #pragma unroll
        for (int jj = 0; jj < 4; jj++)
            #pragma unroll
            for (int ii = 0; ii < 4; ii++)
                Ps[(sc0 + jj) * 68 + (r0 + ii)] = accs[ii][jj] * scale;
        __syncthreads();

        float mv = -1e30f;
        #pragma unroll
        for (int jj = 0; jj < 16; jj++)
            mv = fmaxf(mv, Ps[(q4 + 4 * jj) * 68 + rr]);
        mv = fmaxf(mv, __shfl_xor_sync(0xffffffffu, mv, 1));
        mv = fmaxf(mv, __shfl_xor_sync(0xffffffffu, mv, 2));
        float m_old = m_s[rr];
        float m_new = fmaxf(m_old, mv);
        float sum = 0.0f;
        #pragma unroll
        for (int jj = 0; jj < 16; jj++) {
            int j = q4 + 4 * jj;
            float p = expf(Ps[j * 68 + rr] - m_new);
            Ps[j * 68 + rr] = p;
            sum += p;
        }
        sum += __shfl_xor_sync(0xffffffffu, sum, 1);
        sum += __shfl_xor_sync(0xffffffffu, sum, 2);
        if (q4 == 0) {
            float corr = expf(m_old - m_new);
            l_s[rr] = l_s[rr] * corr + sum;
            m_s[rr] = m_new;
            corr_s[rr] = corr;
        }
        __syncthreads();

        float c_[4] = {corr_s[r0], corr_s[r0 + 1], corr_s[r0 + 2], corr_s[r0 + 3]};
        #pragma unroll
        for (int i = 0; i < 4; i++)
            #pragma unroll
            for (int j = 0; j < 8; j++) acc[i][j] *= c_[i];

        #pragma unroll 4
        for (int j = 0; j < 64; j++) {
            float4 p4 = *(float4*)&Ps[j * 68 + r0];
            float4 v0 = *(float4*)&Vs[j * 132 + d0];
            float4 v1 = *(float4*)&Vs[j * 132 + d0 + 4];
            float pv[4] = {p4.x, p4.y, p4.z, p4.w};
            float vv[8] = {v0.x, v0.y, v0.z, v0.w, v1.x, v1.y, v1.z, v1.w};
            #pragma unroll
            for (int i = 0; i < 4; i++)
                #pragma unroll
                for (int jj = 0; jj < 8; jj++)
                    acc[i][jj] += pv[i] * vv[jj];
        }
        __syncthreads();
    }

    const int b = bh >> 4, h = bh & 15;
    #pragma unroll
    for (int i = 0; i < 4; i++) {
        float inv_l = 1.0f / l_s[r0 + i];
        size_t grow = (size_t)(b * SEQ + s0 + r0 + i) * DMODEL + h * HDIM + d0;
        float4 o0 = make_float4(acc[i][0] * inv_l, acc[i][1] * inv_l,
                                acc[i][2] * inv_l, acc[i][3] * inv_l);
        float4 o1 = make_float4(acc[i][4] * inv_l, acc[i][5] * inv_l,
                                acc[i][6] * inv_l, acc[i][7] * inv_l);
        *(float4*)&Og[grow]     = o0;
        *(float4*)&Og[grow + 4] = o1;
    }
}

// ---------------- launch ----------------
extern "C" void kernel_launch(void* const* d_in, const int* in_sizes, int n_in,
                              void* d_out, int out_size)
{
    const float* x     = (const float*)d_in[0];
    const float* w_qkv = (const float*)d_in[1];
    const float* w_out = (const float*)d_in[2];
    float* out = (float*)d_out;

    float *qkv, *Q, *K, *V, *attn;
    cudaGetSymbolAddress((void**)&qkv,  g_qkv);
    cudaGetSymbolAddress((void**)&Q,    g_Q);
    cudaGetSymbolAddress((void**)&K,    g_K);
    cudaGetSymbolAddress((void**)&V,    g_V);
    cudaGetSymbolAddress((void**)&attn, g_attn);

    cudaFuncSetAttribute(attn_kernel, cudaFuncAttributeMaxDynamicSharedMemorySize,
                         ATTN_SMEM_BYTES);
    cudaFuncSetAttribute(tf32_mma_gemm, cudaFuncAttributeMaxDynamicSharedMemorySize,
                         GMM_SMEM_BYTES);

    rope_table_kernel<<<SEQ, 64>>>();
    // qkv = x @ w_qkv   [4096,2048]x[2048,6144]  (tf32 mma.sync)
    tf32_mma_gemm<<<dim3(D3 / 128, MROWS / 128), 256, GMM_SMEM_BYTES>>>(
        x, w_qkv, qkv, MROWS, D3, DMODEL);
    // rope + split
    rope_split_kernel<<<MROWS, 256>>>(qkv, Q, K, V);
    // attention (fp32, unchanged)
    attn_kernel<<<dim3(SEQ / 64, BATCH * NHEADS), 256, ATTN_SMEM_BYTES>>>(Q, K, V, attn);
    // out = attn @ w_out  [4096,2048]x[2048,2048]  (tf32 mma.sync)
    tf32_mma_gemm<<<dim3(DMODEL / 128, MROWS / 128), 256, GMM_SMEM_BYTES>>>(
        attn, w_out, out, MROWS, DMODEL, DMODEL);
}

// round 8
// speedup vs baseline: 2.5050x; 1.7026x over previous
#include <cuda_runtime.h>
#include <cstddef>
#include <cstdint>

// Problem constants
#define BATCH 2
#define SEQ   2048
#define DMODEL 2048
#define NHEADS 16
#define HDIM  128
#define D3    (3 * DMODEL)
#define MROWS (BATCH * SEQ)   // 4096

// ---------------- scratch (no allocations allowed) ----------------
__device__ float g_qkv[(size_t)MROWS * D3];                       // [B*S, 3D]
__device__ float g_Q[(size_t)BATCH * NHEADS * SEQ * HDIM];        // [B,H,S,hd]
__device__ float g_K[(size_t)BATCH * NHEADS * SEQ * HDIM];
__device__ float g_V[(size_t)BATCH * NHEADS * SEQ * HDIM];
__device__ float g_attn[(size_t)MROWS * DMODEL];                  // [B*S, D]
__device__ float g_cos[SEQ * 64];
__device__ float g_sin[SEQ * 64];

// ---------------- helpers ----------------
__device__ __forceinline__ float to_tf32(float x) {
    float r;
    asm("cvt.rna.tf32.f32 %0, %1;" : "=f"(r) : "f"(x));
    return r;
}

// m16n8k8 tf32 warp MMA (base PTX, sm_80+)
__device__ __forceinline__ void mma_tf32(float c[4],
                                         uint32_t a0, uint32_t a1, uint32_t a2, uint32_t a3,
                                         uint32_t b0, uint32_t b1) {
    asm volatile(
        "mma.sync.aligned.m16n8k8.row.col.f32.tf32.tf32.f32 "
        "{%0,%1,%2,%3}, {%4,%5,%6,%7}, {%8,%9}, {%0,%1,%2,%3};"
        : "+f"(c[0]), "+f"(c[1]), "+f"(c[2]), "+f"(c[3])
        : "r"(a0), "r"(a1), "r"(a2), "r"(a3), "r"(b0), "r"(b1));
}

// ---------------- RoPE table ----------------
__global__ void rope_table_kernel() {
    int s = blockIdx.x;
    int j = threadIdx.x;            // 0..63
    float inv = powf(10000.0f, -(float)j / 64.0f);
    float ang = (float)s * inv;
    g_cos[s * 64 + j] = cosf(ang);
    g_sin[s * 64 + j] = sinf(ang);
}

// ================= tf32 mma.sync GEMM (unchanged, known-good) =================
#define GMM_A_STRIDE 36
#define GMM_B_STRIDE 136
#define GMM_A_FLOATS (128 * GMM_A_STRIDE)   // 4608
#define GMM_B_FLOATS (32 * GMM_B_STRIDE)    // 4352
#define GMM_SMEM_FLOATS (2 * GMM_A_FLOATS + 2 * GMM_B_FLOATS)   // 17920
#define GMM_SMEM_BYTES  (GMM_SMEM_FLOATS * 4)                   // 71680

__global__ __launch_bounds__(256) void tf32_mma_gemm(
    const float* __restrict__ A, const float* __restrict__ B, float* __restrict__ C,
    int M, int N, int K_)
{
    extern __shared__ float sm[];
    float* Asm = sm;                        // [2][128][36]
    float* Bsm = sm + 2 * GMM_A_FLOATS;     // [2][32][136]

    const int tid = threadIdx.x;
    const int wid = tid >> 5, lane = tid & 31;
    const int g = lane >> 2, t = lane & 3;
    const int wm = wid >> 2, wn = wid & 3;
    const int m0 = blockIdx.y * 128, n0 = blockIdx.x * 128;
    const int mbase = wm * 64, nbase = wn * 32;

    float4 apref[4], bpref[4];

    #define LOADG(kt) do { \
        _Pragma("unroll") \
        for (int i = 0; i < 4; i++) { \
            int f4 = tid + i * 256; \
            int r = f4 >> 3, c = (f4 & 7) << 2; \
            apref[i] = *(const float4*)&A[(size_t)(m0 + r) * K_ + (kt) * 32 + c]; \
            int rb = f4 >> 5, cb = (f4 & 31) << 2; \
            bpref[i] = *(const float4*)&B[(size_t)((kt) * 32 + rb) * N + n0 + cb]; \
        } \
    } while (0)

    #define STORES(buf) do { \
        _Pragma("unroll") \
        for (int i = 0; i < 4; i++) { \
            int f4 = tid + i * 256; \
            int r = f4 >> 3, c = (f4 & 7) << 2; \
            float4 v = apref[i]; \
            v.x = to_tf32(v.x); v.y = to_tf32(v.y); v.z = to_tf32(v.z); v.w = to_tf32(v.w); \
            *(float4*)&Asm[(buf) * GMM_A_FLOATS + r * GMM_A_STRIDE + c] = v; \
            int rb = f4 >> 5, cb = (f4 & 31) << 2; \
            float4 w = bpref[i]; \
            w.x = to_tf32(w.x); w.y = to_tf32(w.y); w.z = to_tf32(w.z); w.w = to_tf32(w.w); \
            *(float4*)&Bsm[(buf) * GMM_B_FLOATS + rb * GMM_B_STRIDE + cb] = w; \
        } \
    } while (0)

    float acc[4][4][4];
    #pragma unroll
    for (int mf = 0; mf < 4; mf++)
        #pragma unroll
        for (int nf = 0; nf < 4; nf++)
            #pragma unroll
            for (int q = 0; q < 4; q++) acc[mf][nf][q] = 0.0f;

    const int KT = K_ / 32;
    LOADG(0);
    STORES(0);
    __syncthreads();

    for (int kt = 0; kt < KT; kt++) {
        const int buf = kt & 1;
        if (kt + 1 < KT) LOADG(kt + 1);

        const float* Ab = &Asm[buf * GMM_A_FLOATS];
        const float* Bb = &Bsm[buf * GMM_B_FLOATS];
        #pragma unroll
        for (int ks = 0; ks < 4; ks++) {
            const int k = ks * 8;
            uint32_t af[4][4];
            #pragma unroll
            for (int mf = 0; mf < 4; mf++) {
                const int row = mbase + mf * 16 + g;
                af[mf][0] = __float_as_uint(Ab[row * GMM_A_STRIDE + k + t]);
                af[mf][1] = __float_as_uint(Ab[(row + 8) * GMM_A_STRIDE + k + t]);
                af[mf][2] = __float_as_uint(Ab[row * GMM_A_STRIDE + k + t + 4]);
                af[mf][3] = __float_as_uint(Ab[(row + 8) * GMM_A_STRIDE + k + t + 4]);
            }
            uint32_t bfr[4][2];
            #pragma unroll
            for (int nf = 0; nf < 4; nf++) {
                const int col = nbase + nf * 8 + g;
                bfr[nf][0] = __float_as_uint(Bb[(k + t) * GMM_B_STRIDE + col]);
                bfr[nf][1] = __float_as_uint(Bb[(k + t + 4) * GMM_B_STRIDE + col]);
            }
            #pragma unroll
            for (int mf = 0; mf < 4; mf++)
                #pragma unroll
                for (int nf = 0; nf < 4; nf++)
                    mma_tf32(acc[mf][nf], af[mf][0], af[mf][1], af[mf][2], af[mf][3],
                             bfr[nf][0], bfr[nf][1]);
        }

        if (kt + 1 < KT) {
            STORES(buf ^ 1);
            __syncthreads();
        }
    }

    #pragma unroll
    for (int mf = 0; mf < 4; mf++) {
        #pragma unroll
        for (int nf = 0; nf < 4; nf++) {
            const int row = m0 + mbase + mf * 16 + g;
            const int col = n0 + nbase + nf * 8 + 2 * t;
            *(float2*)&C[(size_t)row * N + col] =
                make_float2(acc[mf][nf][0], acc[mf][nf][1]);
            *(float2*)&C[(size_t)(row + 8) * N + col] =
                make_float2(acc[mf][nf][2], acc[mf][nf][3]);
        }
    }
    #undef LOADG
    #undef STORES
}

// ---------------- RoPE + split + transpose ----------------
__global__ __launch_bounds__(256) void rope_split_kernel(
    const float* __restrict__ qkv,
    float* __restrict__ Q, float* __restrict__ K, float* __restrict__ V)
{
    int bs = blockIdx.x;
    int b = bs / SEQ, s = bs % SEQ;
    const float* row = qkv + (size_t)bs * D3;

    for (int e = threadIdx.x; e < DMODEL; e += 256) {
        int h = e >> 7, d = e & 127, j = d & 63;
        float c  = g_cos[s * 64 + j];
        float sn = g_sin[s * 64 + j];
        float qv = row[e];
        float kv = row[DMODEL + e];
        float vv = row[2 * DMODEL + e];
        int po = (d < 64) ? (e + 64) : (e - 64);
        float sgn = (d < 64) ? -1.0f : 1.0f;
        float qp = row[po];
        float kp = row[DMODEL + po];
        float qo = qv * c + sgn * qp * sn;
        float ko = kv * c + sgn * kp * sn;
        size_t oidx = ((size_t)(b * NHEADS + h) * SEQ + s) * HDIM + d;
        Q[oidx] = qo;
        K[oidx] = ko;
        V[oidx] = vv;
    }
}

// ================= tensor-core flash attention (tf32 mma.sync) =================
// q-tile 64, kv-tile 64, 256 threads (8 warps: 4m x 2n).
// QK^T: 3xtf32 (Q,K hi/lo split) -> fp32-quality logits.
// PV:   2-mma (P hi/lo split, V plain tf32).
// Strides: 132 = 4 (mod 32) -> (4g+t) conflict-free; 136 = 8 -> (8t+g); 68 = 4.
#define AT_QHI  0
#define AT_QLO  (AT_QHI + 64 * 132)     // 8448
#define AT_KHI  (AT_QLO + 64 * 132)     // 16896
#define AT_KLO  (AT_KHI + 64 * 132)     // 25344
#define AT_V    (AT_KLO + 64 * 132)     // 33792
#define AT_PHI  (AT_V + 64 * 136)       // 42496
#define AT_PLO  (AT_PHI + 64 * 68)      // 46848
#define AT_RMAX (AT_PLO + 64 * 68)      // 51200  [2][64]
#define AT_RSUM (AT_RMAX + 128)         // 51328  [2][64]
#define AT_FLOATS (AT_RSUM + 128)       // 51456
#define AT_BYTES  (AT_FLOATS * 4)       // 205824

__global__ __launch_bounds__(256, 1) void attn_mma_kernel(
    const float* __restrict__ Qg, const float* __restrict__ Kg,
    const float* __restrict__ Vg, float* __restrict__ Og)
{
    extern __shared__ float sm[];
    const int tid = threadIdx.x;
    const int wid = tid >> 5, lane = tid & 31;
    const int g = lane >> 2, t = lane & 3;
    const int wm = wid >> 1, wn = wid & 1;
    const int qb = wm * 16;                 // warp's 16-row q band
    const int bh = blockIdx.y;
    const int s0 = blockIdx.x * 64;
    const float* Qb = Qg + (size_t)bh * SEQ * HDIM;
    const float* Kb = Kg + (size_t)bh * SEQ * HDIM;
    const float* Vb = Vg + (size_t)bh * SEQ * HDIM;
    const float SCL2E = 0.08838834764831845f * 1.4426950408889634f; // scale*log2e

    // ---- load Q tile, hi/lo split ----
    #pragma unroll
    for (int i = 0; i < 8; i++) {
        int f4 = tid + i * 256;             // 0..2047
        int r = f4 >> 5, c4 = (f4 & 31) << 2;
        float4 v = *(const float4*)&Qb[(size_t)(s0 + r) * HDIM + c4];
        float4 hi, lo;
        hi.x = to_tf32(v.x); lo.x = to_tf32(v.x - hi.x);
        hi.y = to_tf32(v.y); lo.y = to_tf32(v.y - hi.y);
        hi.z = to_tf32(v.z); lo.z = to_tf32(v.z - hi.z);
        hi.w = to_tf32(v.w); lo.w = to_tf32(v.w - hi.w);
        *(float4*)&sm[AT_QHI + r * 132 + c4] = hi;
        *(float4*)&sm[AT_QLO + r * 132 + c4] = lo;
    }
    __syncthreads();

    float m0 = -1e30f, m1 = -1e30f, l0 = 0.0f, l1 = 0.0f;
    float acc[8][4];
    #pragma unroll
    for (int nf = 0; nf < 8; nf++)
        #pragma unroll
        for (int q = 0; q < 4; q++) acc[nf][q] = 0.0f;

    for (int kt = 0; kt < SEQ / 64; kt++) {
        const int ks0 = kt * 64;
        // ---- load K (hi/lo) and V (tf32) tiles ----
        #pragma unroll
        for (int i = 0; i < 8; i++) {
            int f4 = tid + i * 256;
            int r = f4 >> 5, c4 = (f4 & 31) << 2;
            float4 kv = *(const float4*)&Kb[(size_t)(ks0 + r) * HDIM + c4];
            float4 hi, lo;
            hi.x = to_tf32(kv.x); lo.x = to_tf32(kv.x - hi.x);
            hi.y = to_tf32(kv.y); lo.y = to_tf32(kv.y - hi.y);
            hi.z = to_tf32(kv.z); lo.z = to_tf32(kv.z - hi.z);
            hi.w = to_tf32(kv.w); lo.w = to_tf32(kv.w - hi.w);
            *(float4*)&sm[AT_KHI + r * 132 + c4] = hi;
            *(float4*)&sm[AT_KLO + r * 132 + c4] = lo;
            float4 vv = *(const float4*)&Vb[(size_t)(ks0 + r) * HDIM + c4];
            vv.x = to_tf32(vv.x); vv.y = to_tf32(vv.y);
            vv.z = to_tf32(vv.z); vv.w = to_tf32(vv.w);
            *(float4*)&sm[AT_V + r * 136 + c4] = vv;
        }
        __syncthreads();

        // ---- S = Q K^T (3xtf32), warp tile 16q x 32kv ----
        float sfr[4][4];
        #pragma unroll
        for (int nf = 0; nf < 4; nf++)
            #pragma unroll
            for (int q = 0; q < 4; q++) sfr[nf][q] = 0.0f;

        #pragma unroll
        for (int ks = 0; ks < 16; ks++) {
            const int k = ks * 8;
            const int r0 = qb + g;
            uint32_t ah[4], al[4];
            ah[0] = __float_as_uint(sm[AT_QHI + r0 * 132 + k + t]);
            ah[1] = __float_as_uint(sm[AT_QHI + (r0 + 8) * 132 + k + t]);
            ah[2] = __float_as_uint(sm[AT_QHI + r0 * 132 + k + t + 4]);
            ah[3] = __float_as_uint(sm[AT_QHI + (r0 + 8) * 132 + k + t + 4]);
            al[0] = __float_as_uint(sm[AT_QLO + r0 * 132 + k + t]);
            al[1] = __float_as_uint(sm[AT_QLO + (r0 + 8) * 132 + k + t]);
            al[2] = __float_as_uint(sm[AT_QLO + r0 * 132 + k + t + 4]);
            al[3] = __float_as_uint(sm[AT_QLO + (r0 + 8) * 132 + k + t + 4]);
            #pragma unroll
            for (int nf = 0; nf < 4; nf++) {
                const int col = wn * 32 + nf * 8 + g;
                uint32_t bh0 = __float_as_uint(sm[AT_KHI + col * 132 + k + t]);
                uint32_t bh1 = __float_as_uint(sm[AT_KHI + col * 132 + k + t + 4]);
                uint32_t bl0 = __float_as_uint(sm[AT_KLO + col * 132 + k + t]);
                uint32_t bl1 = __float_as_uint(sm[AT_KLO + col * 132 + k + t + 4]);
                mma_tf32(sfr[nf], ah[0], ah[1], ah[2], ah[3], bh0, bh1);
                mma_tf32(sfr[nf], ah[0], ah[1], ah[2], ah[3], bl0, bl1);
                mma_tf32(sfr[nf], al[0], al[1], al[2], al[3], bh0, bh1);
            }
        }

        // ---- online softmax (log2 domain) ----
        #pragma unroll
        for (int nf = 0; nf < 4; nf++)
            #pragma unroll
            for (int q = 0; q < 4; q++) sfr[nf][q] *= SCL2E;

        float mx0 = -1e30f, mx1 = -1e30f;
        #pragma unroll
        for (int nf = 0; nf < 4; nf++) {
            mx0 = fmaxf(mx0, fmaxf(sfr[nf][0], sfr[nf][1]));
            mx1 = fmaxf(mx1, fmaxf(sfr[nf][2], sfr[nf][3]));
        }
        mx0 = fmaxf(mx0, __shfl_xor_sync(0xffffffffu, mx0, 1));
        mx0 = fmaxf(mx0, __shfl_xor_sync(0xffffffffu, mx0, 2));
        mx1 = fmaxf(mx1, __shfl_xor_sync(0xffffffffu, mx1, 1));
        mx1 = fmaxf(mx1, __shfl_xor_sync(0xffffffffu, mx1, 2));
        if (t == 0) {
            sm[AT_RMAX + wn * 64 + qb + g]     = mx0;
            sm[AT_RMAX + wn * 64 + qb + g + 8] = mx1;
        }
        __syncthreads();
        float mn0 = fmaxf(m0, fmaxf(sm[AT_RMAX + qb + g],
                                    sm[AT_RMAX + 64 + qb + g]));
        float mn1 = fmaxf(m1, fmaxf(sm[AT_RMAX + qb + g + 8],
                                    sm[AT_RMAX + 64 + qb + g + 8]));
        float corr0 = exp2f(m0 - mn0);
        float corr1 = exp2f(m1 - mn1);
        m0 = mn0; m1 = mn1;

        float sum0 = 0.0f, sum1 = 0.0f;
        #pragma unroll
        for (int nf = 0; nf < 4; nf++) {
            float p0 = exp2f(sfr[nf][0] - mn0);
            float p1 = exp2f(sfr[nf][1] - mn0);
            float p2 = exp2f(sfr[nf][2] - mn1);
            float p3 = exp2f(sfr[nf][3] - mn1);
            sum0 += p0 + p1;
            sum1 += p2 + p3;
            float h0 = to_tf32(p0), h1 = to_tf32(p1);
            float h2 = to_tf32(p2), h3 = to_tf32(p3);
            const int colb = wn * 32 + nf * 8 + 2 * t;
            *(float2*)&sm[AT_PHI + (qb + g) * 68 + colb]     = make_float2(h0, h1);
            *(float2*)&sm[AT_PHI + (qb + g + 8) * 68 + colb] = make_float2(h2, h3);
            *(float2*)&sm[AT_PLO + (qb + g) * 68 + colb] =
                make_float2(to_tf32(p0 - h0), to_tf32(p1 - h1));
            *(float2*)&sm[AT_PLO + (qb + g + 8) * 68 + colb] =
                make_float2(to_tf32(p2 - h2), to_tf32(p3 - h3));
        }
        sum0 += __shfl_xor_sync(0xffffffffu, sum0, 1);
        sum0 += __shfl_xor_sync(0xffffffffu, sum0, 2);
        sum1 += __shfl_xor_sync(0xffffffffu, sum1, 1);
        sum1 += __shfl_xor_sync(0xffffffffu, sum1, 2);
        if (t == 0) {
            sm[AT_RSUM + wn * 64 + qb + g]     = sum0;
            sm[AT_RSUM + wn * 64 + qb + g + 8] = sum1;
        }
        // rescale O accumulator
        #pragma unroll
        for (int nf = 0; nf < 8; nf++) {
            acc[nf][0] *= corr0; acc[nf][1] *= corr0;
            acc[nf][2] *= corr1; acc[nf][3] *= corr1;
        }
        __syncthreads();   // P + RSUM visible
        l0 = l0 * corr0 + sm[AT_RSUM + qb + g]     + sm[AT_RSUM + 64 + qb + g];
        l1 = l1 * corr1 + sm[AT_RSUM + qb + g + 8] + sm[AT_RSUM + 64 + qb + g + 8];

        // ---- O += P V (2-mma split-P), warp tile 16q x 64d ----
        #pragma unroll
        for (int ks = 0; ks < 8; ks++) {
            const int k = ks * 8;
            const int r0 = qb + g;
            uint32_t ah[4], al[4];
            ah[0] = __float_as_uint(sm[AT_PHI + r0 * 68 + k + t]);
            ah[1] = __float_as_uint(sm[AT_PHI + (r0 + 8) * 68 + k + t]);
            ah[2] = __float_as_uint(sm[AT_PHI + r0 * 68 + k + t + 4]);
            ah[3] = __float_as_uint(sm[AT_PHI + (r0 + 8) * 68 + k + t + 4]);
            al[0] = __float_as_uint(sm[AT_PLO + r0 * 68 + k + t]);
            al[1] = __float_as_uint(sm[AT_PLO + (r0 + 8) * 68 + k + t]);
            al[2] = __float_as_uint(sm[AT_PLO + r0 * 68 + k + t + 4]);
            al[3] = __float_as_uint(sm[AT_PLO + (r0 + 8) * 68 + k + t + 4]);
            #pragma unroll
            for (int nf = 0; nf < 8; nf++) {
                const int col = wn * 64 + nf * 8 + g;
                uint32_t b0 = __float_as_uint(sm[AT_V + (k + t) * 136 + col]);
                uint32_t b1 = __float_as_uint(sm[AT_V + (k + t + 4) * 136 + col]);
                mma_tf32(acc[nf], ah[0], ah[1], ah[2], ah[3], b0, b1);
                mma_tf32(acc[nf], al[0], al[1], al[2], al[3], b0, b1);
            }
        }
        __syncthreads();   // before next tile overwrites K/V/P
    }

    // ---- epilogue: normalize, write [B*S, D] (col = h*128 + d) ----
    const float rl0 = 1.0f / l0, rl1 = 1.0f / l1;
    const int b = bh >> 4, h = bh & 15;
    const size_t base0 = (size_t)(b * SEQ + s0 + qb + g) * DMODEL + h * HDIM;
    const size_t base1 = (size_t)(b * SEQ + s0 + qb + g + 8) * DMODEL + h * HDIM;
    #pragma unroll
    for (int nf = 0; nf < 8; nf++) {
        const int colb = wn * 64 + nf * 8 + 2 * t;
        *(float2*)&Og[base0 + colb] = make_float2(acc[nf][0] * rl0, acc[nf][1] * rl0);
        *(float2*)&Og[base1 + colb] = make_float2(acc[nf][2] * rl1, acc[nf][3] * rl1);
    }
}

// ---------------- launch ----------------
extern "C" void kernel_launch(void* const* d_in, const int* in_sizes, int n_in,
                              void* d_out, int out_size)
{
    const float* x     = (const float*)d_in[0];
    const float* w_qkv = (const float*)d_in[1];
    const float* w_out = (const float*)d_in[2];
    float* out = (float*)d_out;

    float *qkv, *Q, *K, *V, *attn;
    cudaGetSymbolAddress((void**)&qkv,  g_qkv);
    cudaGetSymbolAddress((void**)&Q,    g_Q);
    cudaGetSymbolAddress((void**)&K,    g_K);
    cudaGetSymbolAddress((void**)&V,    g_V);
    cudaGetSymbolAddress((void**)&attn, g_attn);

    cudaFuncSetAttribute(tf32_mma_gemm, cudaFuncAttributeMaxDynamicSharedMemorySize,
                         GMM_SMEM_BYTES);
    cudaFuncSetAttribute(attn_mma_kernel, cudaFuncAttributeMaxDynamicSharedMemorySize,
                         AT_BYTES);

    rope_table_kernel<<<SEQ, 64>>>();
    // qkv = x @ w_qkv   [4096,2048]x[2048,6144]  (tf32 mma.sync)
    tf32_mma_gemm<<<dim3(D3 / 128, MROWS / 128), 256, GMM_SMEM_BYTES>>>(
        x, w_qkv, qkv, MROWS, D3, DMODEL);
    // rope + split
    rope_split_kernel<<<MROWS, 256>>>(qkv, Q, K, V);
    // attention (tensor-core flash, 3xtf32 QK^T, split-P PV)
    attn_mma_kernel<<<dim3(SEQ / 64, BATCH * NHEADS), 256, AT_BYTES>>>(Q, K, V, attn);
    // out = attn @ w_out  [4096,2048]x[2048,2048]  (tf32 mma.sync)
    tf32_mma_gemm<<<dim3(DMODEL / 128, MROWS / 128), 256, GMM_SMEM_BYTES>>>(
        attn, w_out, out, MROWS, DMODEL, DMODEL);
}

// round 11
// speedup vs baseline: 2.9748x; 1.1875x over previous
#include <cuda_runtime.h>
#include <cuda_bf16.h>
#include <cstddef>
#include <cstdint>

// Problem constants
#define BATCH 2
#define SEQ   2048
#define DMODEL 2048
#define NHEADS 16
#define HDIM  128
#define D3    (3 * DMODEL)
#define MROWS (BATCH * SEQ)   // 4096

// ---------------- scratch (no allocations allowed) ----------------
__device__ float g_qkv[(size_t)MROWS * D3];                       // [B*S, 3D]
__device__ float g_Q[(size_t)BATCH * NHEADS * SEQ * HDIM];        // [B,H,S,hd]
__device__ float g_K[(size_t)BATCH * NHEADS * SEQ * HDIM];
__device__ float g_V[(size_t)BATCH * NHEADS * SEQ * HDIM];
__device__ float g_attn[(size_t)MROWS * DMODEL];                  // [B*S, D]
__device__ float g_cos[SEQ * 64];
__device__ float g_sin[SEQ * 64];

// ---------------- helpers ----------------
__device__ __forceinline__ float to_tf32(float x) {
    float r;
    asm("cvt.rna.tf32.f32 %0, %1;" : "=f"(r) : "f"(x));
    return r;
}

// m16n8k8 tf32 warp MMA (base PTX, sm_80+)
__device__ __forceinline__ void mma_tf32(float c[4],
                                         uint32_t a0, uint32_t a1, uint32_t a2, uint32_t a3,
                                         uint32_t b0, uint32_t b1) {
    asm volatile(
        "mma.sync.aligned.m16n8k8.row.col.f32.tf32.tf32.f32 "
        "{%0,%1,%2,%3}, {%4,%5,%6,%7}, {%8,%9}, {%0,%1,%2,%3};"
        : "+f"(c[0]), "+f"(c[1]), "+f"(c[2]), "+f"(c[3])
        : "r"(a0), "r"(a1), "r"(a2), "r"(a3), "r"(b0), "r"(b1));
}

// m16n8k16 bf16 warp MMA (base PTX, sm_80+)
__device__ __forceinline__ void mma_bf16(float c[4],
                                         uint32_t a0, uint32_t a1, uint32_t a2, uint32_t a3,
                                         uint32_t b0, uint32_t b1) {
    asm volatile(
        "mma.sync.aligned.m16n8k16.row.col.f32.bf16.bf16.f32 "
        "{%0,%1,%2,%3}, {%4,%5,%6,%7}, {%8,%9}, {%0,%1,%2,%3};"
        : "+f"(c[0]), "+f"(c[1]), "+f"(c[2]), "+f"(c[3])
        : "r"(a0), "r"(a1), "r"(a2), "r"(a3), "r"(b0), "r"(b1));
}

// pack two fp32 -> bf16x2 reg (lo_elem -> bits[15:0], hi_elem -> bits[31:16])
__device__ __forceinline__ uint32_t pk2(float lo_elem, float hi_elem) {
    uint32_t r;
    asm("cvt.rn.bf16x2.f32 %0, %1, %2;" : "=r"(r) : "f"(hi_elem), "f"(lo_elem));
    return r;
}
__device__ __forceinline__ float bf16rt(float x) {
    return __bfloat162float(__float2bfloat16(x));
}

// ---------------- RoPE table ----------------
__global__ void rope_table_kernel() {
    int s = blockIdx.x;
    int j = threadIdx.x;            // 0..63
    float inv = powf(10000.0f, -(float)j / 64.0f);
    float ang = (float)s * inv;
    g_cos[s * 64 + j] = cosf(ang);
    g_sin[s * 64 + j] = sinf(ang);
}

// ================= tf32 mma.sync GEMM (unchanged, known-good) =================
#define GMM_A_STRIDE 36
#define GMM_B_STRIDE 136
#define GMM_A_FLOATS (128 * GMM_A_STRIDE)   // 4608
#define GMM_B_FLOATS (32 * GMM_B_STRIDE)    // 4352
#define GMM_SMEM_FLOATS (2 * GMM_A_FLOATS + 2 * GMM_B_FLOATS)   // 17920
#define GMM_SMEM_BYTES  (GMM_SMEM_FLOATS * 4)                   // 71680

__global__ __launch_bounds__(256) void tf32_mma_gemm(
    const float* __restrict__ A, const float* __restrict__ B, float* __restrict__ C,
    int M, int N, int K_)
{
    extern __shared__ float sm[];
    float* Asm = sm;                        // [2][128][36]
    float* Bsm = sm + 2 * GMM_A_FLOATS;     // [2][32][136]

    const int tid = threadIdx.x;
    const int wid = tid >> 5, lane = tid & 31;
    const int g = lane >> 2, t = lane & 3;
    const int wm = wid >> 2, wn = wid & 3;
    const int m0 = blockIdx.y * 128, n0 = blockIdx.x * 128;
    const int mbase = wm * 64, nbase = wn * 32;

    float4 apref[4], bpref[4];

    #define LOADG(kt) do { \
        _Pragma("unroll") \
        for (int i = 0; i < 4; i++) { \
            int f4 = tid + i * 256; \
            int r = f4 >> 3, c = (f4 & 7) << 2; \
            apref[i] = *(const float4*)&A[(size_t)(m0 + r) * K_ + (kt) * 32 + c]; \
            int rb = f4 >> 5, cb = (f4 & 31) << 2; \
            bpref[i] = *(const float4*)&B[(size_t)((kt) * 32 + rb) * N + n0 + cb]; \
        } \
    } while (0)

    #define STORES(buf) do { \
        _Pragma("unroll") \
        for (int i = 0; i < 4; i++) { \
            int f4 = tid + i * 256; \
            int r = f4 >> 3, c = (f4 & 7) << 2; \
            float4 v = apref[i]; \
            v.x = to_tf32(v.x); v.y = to_tf32(v.y); v.z = to_tf32(v.z); v.w = to_tf32(v.w); \
            *(float4*)&Asm[(buf) * GMM_A_FLOATS + r * GMM_A_STRIDE + c] = v; \
            int rb = f4 >> 5, cb = (f4 & 31) << 2; \
            float4 w = bpref[i]; \
            w.x = to_tf32(w.x); w.y = to_tf32(w.y); w.z = to_tf32(w.z); w.w = to_tf32(w.w); \
            *(float4*)&Bsm[(buf) * GMM_B_FLOATS + rb * GMM_B_STRIDE + cb] = w; \
        } \
    } while (0)

    float acc[4][4][4];
    #pragma unroll
    for (int mf = 0; mf < 4; mf++)
        #pragma unroll
        for (int nf = 0; nf < 4; nf++)
            #pragma unroll
            for (int q = 0; q < 4; q++) acc[mf][nf][q] = 0.0f;

    const int KT = K_ / 32;
    LOADG(0);
    STORES(0);
    __syncthreads();

    for (int kt = 0; kt < KT; kt++) {
        const int buf = kt & 1;
        if (kt + 1 < KT) LOADG(kt + 1);

        const float* Ab = &Asm[buf * GMM_A_FLOATS];
        const float* Bb = &Bsm[buf * GMM_B_FLOATS];
        #pragma unroll
        for (int ks = 0; ks < 4; ks++) {
            const int k = ks * 8;
            uint32_t af[4][4];
            #pragma unroll
            for (int mf = 0; mf < 4; mf++) {
                const int row = mbase + mf * 16 + g;
                af[mf][0] = __float_as_uint(Ab[row * GMM_A_STRIDE + k + t]);
                af[mf][1] = __float_as_uint(Ab[(row + 8) * GMM_A_STRIDE + k + t]);
                af[mf][2] = __float_as_uint(Ab[row * GMM_A_STRIDE + k + t + 4]);
                af[mf][3] = __float_as_uint(Ab[(row + 8) * GMM_A_STRIDE + k + t + 4]);
            }
            uint32_t bfr[4][2];
            #pragma unroll
            for (int nf = 0; nf < 4; nf++) {
                const int col = nbase + nf * 8 + g;
                bfr[nf][0] = __float_as_uint(Bb[(k + t) * GMM_B_STRIDE + col]);
                bfr[nf][1] = __float_as_uint(Bb[(k + t + 4) * GMM_B_STRIDE + col]);
            }
            #pragma unroll
            for (int mf = 0; mf < 4; mf++)
                #pragma unroll
                for (int nf = 0; nf < 4; nf++)
                    mma_tf32(acc[mf][nf], af[mf][0], af[mf][1], af[mf][2], af[mf][3],
                             bfr[nf][0], bfr[nf][1]);
        }

        if (kt + 1 < KT) {
            STORES(buf ^ 1);
            __syncthreads();
        }
    }

    #pragma unroll
    for (int mf = 0; mf < 4; mf++) {
        #pragma unroll
        for (int nf = 0; nf < 4; nf++) {
            const int row = m0 + mbase + mf * 16 + g;
            const int col = n0 + nbase + nf * 8 + 2 * t;
            *(float2*)&C[(size_t)row * N + col] =
                make_float2(acc[mf][nf][0], acc[mf][nf][1]);
            *(float2*)&C[(size_t)(row + 8) * N + col] =
                make_float2(acc[mf][nf][2], acc[mf][nf][3]);
        }
    }
    #undef LOADG
    #undef STORES
}

// ---------------- RoPE + split + transpose ----------------
__global__ __launch_bounds__(256) void rope_split_kernel(
    const float* __restrict__ qkv,
    float* __restrict__ Q, float* __restrict__ K, float* __restrict__ V)
{
    int bs = blockIdx.x;
    int b = bs / SEQ, s = bs % SEQ;
    const float* row = qkv + (size_t)bs * D3;

    for (int e = threadIdx.x; e < DMODEL; e += 256) {
        int h = e >> 7, d = e & 127, j = d & 63;
        float c  = g_cos[s * 64 + j];
        float sn = g_sin[s * 64 + j];
        float qv = row[e];
        float kv = row[DMODEL + e];
        float vv = row[2 * DMODEL + e];
        int po = (d < 64) ? (e + 64) : (e - 64);
        float sgn = (d < 64) ? -1.0f : 1.0f;
        float qp = row[po];
        float kp = row[DMODEL + po];
        float qo = qv * c + sgn * qp * sn;
        float ko = kv * c + sgn * kp * sn;
        size_t oidx = ((size_t)(b * NHEADS + h) * SEQ + s) * HDIM + d;
        Q[oidx] = qo;
        K[oidx] = ko;
        V[oidx] = vv;
    }
}

// ============ bf16 split-precision flash attention (mma.sync m16n8k16) ============
// q-tile 128, kv-tile 64, 256 threads = 8 warps; warp w owns q rows w*16..w*16+15
// and ALL 64 kv columns -> warp-local softmax, P stays in registers.
// QK^T: 3-mma bf16 hi/lo split.  PV: 3-mma bf16 (P split in regs, V split in smem).
// Q/K rows hold 128 d-elements -> stride QST=136 (68 words = 4 mod 32, conflict-free).
// VT rows hold 64 kv-elements  -> stride VST=72  (36 words = 4 mod 32, conflict-free).
// K and VT (V transposed to [d][kv]) are double-buffered.
#define QST 136
#define VST 72
#define S_QHI 0
#define S_QLO (128 * QST)                        // 17408
#define S_KB  (2 * 128 * QST)                    // 34816
#define S_KHI(b) (S_KB + (b) * 2 * 64 * QST)
#define S_KLO(b) (S_KHI(b) + 64 * QST)
#define S_VB  (S_KB + 2 * 2 * 64 * QST)          // 69632
#define S_VHI(b) (S_VB + (b) * 2 * 128 * VST)
#define S_VLO(b) (S_VHI(b) + 128 * VST)
#define ATT_ELEMS (S_VB + 2 * 2 * 128 * VST)     // 106496 bf16
#define ATT_BYTES (ATT_ELEMS * 2)                // 212992

__global__ __launch_bounds__(256, 1) void attn_bf16_kernel(
    const float* __restrict__ Qg, const float* __restrict__ Kg,
    const float* __restrict__ Vg, float* __restrict__ Og)
{
    extern __shared__ __nv_bfloat16 smh[];
    const int tid = threadIdx.x;
    const int w = tid >> 5, lane = tid & 31;
    const int g = lane >> 2, t = lane & 3;
    const int qb = w * 16;
    const int bh = blockIdx.y;
    const int s0 = blockIdx.x * 128;
    const float* Qb = Qg + (size_t)bh * SEQ * HDIM;
    const float* Kb = Kg + (size_t)bh * SEQ * HDIM;
    const float* Vb = Vg + (size_t)bh * SEQ * HDIM;
    const float SCL2E = 0.08838834764831845f * 1.4426950408889634f; // 1/sqrt(128)*log2e

    // ---- load Q tile (128 x 128), hi/lo bf16 split ----
    #pragma unroll
    for (int i = 0; i < 16; i++) {
        int f4 = tid + i * 256;                 // 0..4095
        int r = f4 >> 5, c4 = (f4 & 31) << 2;
        float4 v = *(const float4*)&Qb[(size_t)(s0 + r) * HDIM + c4];
        __nv_bfloat16 h0 = __float2bfloat16(v.x), h1 = __float2bfloat16(v.y);
        __nv_bfloat16 h2 = __float2bfloat16(v.z), h3 = __float2bfloat16(v.w);
        *(__nv_bfloat162*)&smh[S_QHI + r * QST + c4]     = __halves2bfloat162(h0, h1);
        *(__nv_bfloat162*)&smh[S_QHI + r * QST + c4 + 2] = __halves2bfloat162(h2, h3);
        __nv_bfloat16 l0 = __float2bfloat16(v.x - __bfloat162float(h0));
        __nv_bfloat16 l1 = __float2bfloat16(v.y - __bfloat162float(h1));
        __nv_bfloat16 l2 = __float2bfloat16(v.z - __bfloat162float(h2));
        __nv_bfloat16 l3 = __float2bfloat16(v.w - __bfloat162float(h3));
        *(__nv_bfloat162*)&smh[S_QLO + r * QST + c4]     = __halves2bfloat162(l0, l1);
        *(__nv_bfloat162*)&smh[S_QLO + r * QST + c4 + 2] = __halves2bfloat162(l2, l3);
    }

    // ---- tile loader: K [64][128] split + V transposed to [d][kv] split ----
    #define LOAD_TILE(kt, b) do { \
        const int ks0_ = (kt) * 64; \
        _Pragma("unroll") \
        for (int i = 0; i < 8; i++) { \
            int f4 = tid + i * 256; \
            int r = f4 >> 5, c4 = (f4 & 31) << 2; \
            float4 v = *(const float4*)&Kb[(size_t)(ks0_ + r) * HDIM + c4]; \
            __nv_bfloat16 h0 = __float2bfloat16(v.x), h1 = __float2bfloat16(v.y); \
            __nv_bfloat16 h2 = __float2bfloat16(v.z), h3 = __float2bfloat16(v.w); \
            *(__nv_bfloat162*)&smh[S_KHI(b) + r * QST + c4]     = __halves2bfloat162(h0, h1); \
            *(__nv_bfloat162*)&smh[S_KHI(b) + r * QST + c4 + 2] = __halves2bfloat162(h2, h3); \
            __nv_bfloat16 l0 = __float2bfloat16(v.x - __bfloat162float(h0)); \
            __nv_bfloat16 l1 = __float2bfloat16(v.y - __bfloat162float(h1)); \
            __nv_bfloat16 l2 = __float2bfloat16(v.z - __bfloat162float(h2)); \
            __nv_bfloat16 l3 = __float2bfloat16(v.w - __bfloat162float(h3)); \
            *(__nv_bfloat162*)&smh[S_KLO(b) + r * QST + c4]     = __halves2bfloat162(l0, l1); \
            *(__nv_bfloat162*)&smh[S_KLO(b) + r * QST + c4 + 2] = __halves2bfloat162(l2, l3); \
        } \
        _Pragma("unroll") \
        for (int it = 0; it < 32; it++) { \
            int kv = w + 8 * (it >> 2); \
            int d  = ((it & 3) << 5) + lane; \
            float v = Vb[(size_t)(ks0_ + kv) * HDIM + d]; \
            __nv_bfloat16 hv = __float2bfloat16(v); \
            smh[S_VHI(b) + d * VST + kv] = hv; \
            smh[S_VLO(b) + d * VST + kv] = __float2bfloat16(v - __bfloat162float(hv)); \
        } \
    } while (0)

    LOAD_TILE(0, 0);
    __syncthreads();

    float m0 = -1e30f, m1 = -1e30f, l0 = 0.0f, l1 = 0.0f;
    float acc[16][4];
    #pragma unroll
    for (int nf = 0; nf < 16; nf++)
        #pragma unroll
        for (int q = 0; q < 4; q++) acc[nf][q] = 0.0f;

    const uint32_t* QhiW = (const uint32_t*)(smh + S_QHI);
    const uint32_t* QloW = (const uint32_t*)(smh + S_QLO);

    for (int kt = 0; kt < SEQ / 64; kt++) {
        const int buf = kt & 1;
        if (kt + 1 < SEQ / 64) LOAD_TILE(kt + 1, buf ^ 1);

        const uint32_t* KhiW = (const uint32_t*)(smh + S_KHI(buf));
        const uint32_t* KloW = (const uint32_t*)(smh + S_KLO(buf));
        const uint32_t* VhiW = (const uint32_t*)(smh + S_VHI(buf));
        const uint32_t* VloW = (const uint32_t*)(smh + S_VLO(buf));

        // ---- S = Q K^T : 3-mma bf16, 16q x 64kv per warp ----
        float sfr[8][4];
        #pragma unroll
        for (int nf = 0; nf < 8; nf++)
            #pragma unroll
            for (int q = 0; q < 4; q++) sfr[nf][q] = 0.0f;

        #pragma unroll
        for (int ks = 0; ks < 8; ks++) {
            const int aw = (qb + g) * 68 + ks * 8 + t;
            const int aw8 = aw + 8 * 68;
            uint32_t ah0 = QhiW[aw],     ah1 = QhiW[aw8];
            uint32_t ah2 = QhiW[aw + 4], ah3 = QhiW[aw8 + 4];
            uint32_t al0 = QloW[aw],     al1 = QloW[aw8];
            uint32_t al2 = QloW[aw + 4], al3 = QloW[aw8 + 4];
            #pragma unroll
            for (int nf = 0; nf < 8; nf++) {
                const int bw = (nf * 8 + g) * 68 + ks * 8 + t;
                uint32_t bh0 = KhiW[bw], bh1 = KhiW[bw + 4];
                uint32_t bl0 = KloW[bw], bl1 = KloW[bw + 4];
                mma_bf16(sfr[nf], ah0, ah1, ah2, ah3, bh0, bh1);
                mma_bf16(sfr[nf], ah0, ah1, ah2, ah3, bl0, bl1);
                mma_bf16(sfr[nf], al0, al1, al2, al3, bh0, bh1);
            }
        }

        // ---- warp-local online softmax (log2 domain) ----
        #pragma unroll
        for (int nf = 0; nf < 8; nf++)
            #pragma unroll
            for (int q = 0; q < 4; q++) sfr[nf][q] *= SCL2E;

        float mx0 = -1e30f, mx1 = -1e30f;
        #pragma unroll
        for (int nf = 0; nf < 8; nf++) {
            mx0 = fmaxf(mx0, fmaxf(sfr[nf][0], sfr[nf][1]));
            mx1 = fmaxf(mx1, fmaxf(sfr[nf][2], sfr[nf][3]));
        }
        mx0 = fmaxf(mx0, __shfl_xor_sync(0xffffffffu, mx0, 1));
        mx0 = fmaxf(mx0, __shfl_xor_sync(0xffffffffu, mx0, 2));
        mx1 = fmaxf(mx1, __shfl_xor_sync(0xffffffffu, mx1, 1));
        mx1 = fmaxf(mx1, __shfl_xor_sync(0xffffffffu, mx1, 2));

        float mn0 = fmaxf(m0, mx0), mn1 = fmaxf(m1, mx1);
        float corr0 = exp2f(m0 - mn0), corr1 = exp2f(m1 - mn1);
        m0 = mn0; m1 = mn1;

        float sum0 = 0.0f, sum1 = 0.0f;
        #pragma unroll
        for (int nf = 0; nf < 8; nf++) {
            sfr[nf][0] = exp2f(sfr[nf][0] - mn0);
            sfr[nf][1] = exp2f(sfr[nf][1] - mn0);
            sfr[nf][2] = exp2f(sfr[nf][2] - mn1);
            sfr[nf][3] = exp2f(sfr[nf][3] - mn1);
            sum0 += sfr[nf][0] + sfr[nf][1];
            sum1 += sfr[nf][2] + sfr[nf][3];
        }
        sum0 += __shfl_xor_sync(0xffffffffu, sum0, 1);
        sum0 += __shfl_xor_sync(0xffffffffu, sum0, 2);
        sum1 += __shfl_xor_sync(0xffffffffu, sum1, 1);
        sum1 += __shfl_xor_sync(0xffffffffu, sum1, 2);
        l0 = l0 * corr0 + sum0;
        l1 = l1 * corr1 + sum1;

        #pragma unroll
        for (int nf = 0; nf < 16; nf++) {
            acc[nf][0] *= corr0; acc[nf][1] *= corr0;
            acc[nf][2] *= corr1; acc[nf][3] *= corr1;
        }

        // ---- O += P V : 3-mma bf16, P packed straight from C-frags ----
        #pragma unroll
        for (int ks2 = 0; ks2 < 4; ks2++) {
            const float* p0 = sfr[2 * ks2];
            const float* p1 = sfr[2 * ks2 + 1];
            uint32_t ah0 = pk2(p0[0], p0[1]);
            uint32_t ah1 = pk2(p0[2], p0[3]);
            uint32_t ah2 = pk2(p1[0], p1[1]);
            uint32_t ah3 = pk2(p1[2], p1[3]);
            uint32_t al0 = pk2(p0[0] - bf16rt(p0[0]), p0[1] - bf16rt(p0[1]));
            uint32_t al1 = pk2(p0[2] - bf16rt(p0[2]), p0[3] - bf16rt(p0[3]));
            uint32_t al2 = pk2(p1[0] - bf16rt(p1[0]), p1[1] - bf16rt(p1[1]));
            uint32_t al3 = pk2(p1[2] - bf16rt(p1[2]), p1[3] - bf16rt(p1[3]));
            #pragma unroll
            for (int nf = 0; nf < 16; nf++) {
                const int bw = (nf * 8 + g) * 36 + ks2 * 8 + t;
                uint32_t bh0 = VhiW[bw], bh1 = VhiW[bw + 4];
                uint32_t bl0 = VloW[bw], bl1 = VloW[bw + 4];
                mma_bf16(acc[nf], ah0, ah1, ah2, ah3, bh0, bh1);
                mma_bf16(acc[nf], ah0, ah1, ah2, ah3, bl0, bl1);
                mma_bf16(acc[nf], al0, al1, al2, al3, bh0, bh1);
            }
        }
        __syncthreads();
    }

    // ---- epilogue: normalize, write [B*S, D] (col = h*128 + d) ----
    const float rl0 = 1.0f / l0, rl1 = 1.0f / l1;
    const int b = bh >> 4, h = bh & 15;
    const size_t base0 = (size_t)(b * SEQ + s0 + qb + g) * DMODEL + h * HDIM;
    const size_t base1 = (size_t)(b * SEQ + s0 + qb + g + 8) * DMODEL + h * HDIM;
    #pragma unroll
    for (int nf = 0; nf < 16; nf++) {
        const int colb = nf * 8 + 2 * t;
        *(float2*)&Og[base0 + colb] = make_float2(acc[nf][0] * rl0, acc[nf][1] * rl0);
        *(float2*)&Og[base1 + colb] = make_float2(acc[nf][2] * rl1, acc[nf][3] * rl1);
    }
    #undef LOAD_TILE
}

// ---------------- launch ----------------
extern "C" void kernel_launch(void* const* d_in, const int* in_sizes, int n_in,
                              void* d_out, int out_size)
{
    const float* x     = (const float*)d_in[0];
    const float* w_qkv = (const float*)d_in[1];
    const float* w_out = (const float*)d_in[2];
    float* out = (float*)d_out;

    float *qkv, *Q, *K, *V, *attn;
    cudaGetSymbolAddress((void**)&qkv,  g_qkv);
    cudaGetSymbolAddress((void**)&Q,    g_Q);
    cudaGetSymbolAddress((void**)&K,    g_K);
    cudaGetSymbolAddress((void**)&V,    g_V);
    cudaGetSymbolAddress((void**)&attn, g_attn);

    cudaFuncSetAttribute(tf32_mma_gemm, cudaFuncAttributeMaxDynamicSharedMemorySize,
                         GMM_SMEM_BYTES);
    cudaFuncSetAttribute(attn_bf16_kernel, cudaFuncAttributeMaxDynamicSharedMemorySize,
                         ATT_BYTES);

    rope_table_kernel<<<SEQ, 64>>>();
    // qkv = x @ w_qkv   [4096,2048]x[2048,6144]  (tf32 mma.sync)
    tf32_mma_gemm<<<dim3(D3 / 128, MROWS / 128), 256, GMM_SMEM_BYTES>>>(
        x, w_qkv, qkv, MROWS, D3, DMODEL);
    // rope + split
    rope_split_kernel<<<MROWS, 256>>>(qkv, Q, K, V);
    // attention (bf16 split-precision flash, register-resident P)
    attn_bf16_kernel<<<dim3(SEQ / 128, BATCH * NHEADS), 256, ATT_BYTES>>>(Q, K, V, attn);
    // out = attn @ w_out  [4096,2048]x[2048,2048]  (tf32 mma.sync)
    tf32_mma_gemm<<<dim3(DMODEL / 128, MROWS / 128), 256, GMM_SMEM_BYTES>>>(
        attn, w_out, out, MROWS, DMODEL, DMODEL);
}